// round 11
// baseline (speedup 1.0000x reference)
#include <cuda_runtime.h>
#include <cstdint>

#define D_IN  128
#define F_OUT 64
#define N_S_MAX 100000
#define N_T_MAX 20000
#define NNZ_MAX 2000000
#define CAP_ROW 512    // per-target-segment capacity (mean 100, std 10)
#define CAP_COL 128    // per-source-segment capacity (mean 20, std 4.5)

// ---------------- scratch (static device globals; no allocs) ----------------
__device__ float g_s_msg[(size_t)N_S_MAX * F_OUT];   // 25.6 MB
__device__ float g_t_msg[(size_t)N_T_MAX * F_OUT];   // 5.1 MB
__device__ float g_s_score[N_S_MAX];
__device__ float g_t_score[N_T_MAX];
__device__ float g_e_row_sum[N_T_MAX];               // fp32, folded in edge order
__device__ float g_f_row_sum[N_S_MAX];
__device__ float g_edge[NNZ_MAX];                    // 8 MB
__device__ int   g_row_cnt[N_T_MAX];
__device__ int   g_col_cnt[N_S_MAX];
__device__ int   g_row_ids[(size_t)N_T_MAX * CAP_ROW];   // 41 MB
__device__ int   g_col_ids[(size_t)N_S_MAX * CAP_COL];   // 51 MB

// ---------------- helpers ----------------
__device__ __forceinline__ void red_add_v4(float* addr, float a, float b, float c, float d) {
    asm volatile("red.global.add.v4.f32 [%0], {%1,%2,%3,%4};"
                 :: "l"(addr), "f"(a), "f"(b), "f"(c), "f"(d)
                 : "memory");
}

// ---------------- zero init ----------------
__global__ void zero_kernel(float4* __restrict__ out4, int n_out4, int n_t, int n_s) {
    int stride = gridDim.x * blockDim.x;
    int tid = blockIdx.x * blockDim.x + threadIdx.x;
    float4 z = make_float4(0.f, 0.f, 0.f, 0.f);
    for (int j = tid; j < n_out4; j += stride) out4[j] = z;
    for (int j = tid; j < n_t; j += stride) g_row_cnt[j] = 0;
    for (int j = tid; j < n_s; j += stride) g_col_cnt[j] = 0;
}

// ---------------- fused GEMM + Eigen-3.4-gemv score ----------------
// C[M x 64] = X[M x 128] @ W[128 x 64]: strict ascending-k single-accumulator
// fmaf chain per element (Eigen gebp semantics).
// score[m]: Eigen 3.4 general_matrix_vector_product<RowMajor> emulation:
// column loop unrolled by 4 packets (16 lanes). Lane (q,l) accumulates
// n = 16p + 4q + l, p ascending (fma). Combine:
//   v = padd(padd(c0,c1), padd(c2,c3))   [per-lane l]
//   score = predux(v) = vaddvq = (v0+v1) + (v2+v3)
__global__ void __launch_bounds__(256) gemm_fused(
    const float* __restrict__ X, const float* __restrict__ W,
    const float* __restrict__ avec,
    float* __restrict__ C, float* __restrict__ score, int M)
{
    __shared__ float sX[128][33];
    __shared__ float sW[32][F_OUT];
    __shared__ float sC[128][F_OUT + 1];
    __shared__ float sA[F_OUT];

    const int tid = threadIdx.x;
    const int tx = tid & 15;       // col group (4 cols)
    const int ty = tid >> 4;       // row group (8 rows)
    const int rowBase = blockIdx.x * 128;

    if (tid < F_OUT) sA[tid] = avec[tid];

    float acc[8][4];
#pragma unroll
    for (int i = 0; i < 8; i++) { acc[i][0] = acc[i][1] = acc[i][2] = acc[i][3] = 0.f; }

    for (int kc = 0; kc < D_IN; kc += 32) {
        {
            const float4* Wg = (const float4*)(W + kc * F_OUT);
            float4* sW4 = (float4*)(&sW[0][0]);
#pragma unroll
            for (int t = tid; t < 32 * F_OUT / 4; t += 256) sW4[t] = Wg[t];
        }
#pragma unroll
        for (int t = tid; t < 128 * 8; t += 256) {
            int r  = t >> 3;
            int k4 = (t & 7) * 4;
            int grow = rowBase + r;
            float4 v = make_float4(0.f, 0.f, 0.f, 0.f);
            if (grow < M) v = *(const float4*)(X + (size_t)grow * D_IN + kc + k4);
            sX[r][k4 + 0] = v.x; sX[r][k4 + 1] = v.y;
            sX[r][k4 + 2] = v.z; sX[r][k4 + 3] = v.w;
        }
        __syncthreads();
        // strict ascending k, one fmaf per k per element (order-exact chain)
#pragma unroll
        for (int kk = 0; kk < 32; kk++) {
            float wv[4], xv[8];
#pragma unroll
            for (int j = 0; j < 4; j++) wv[j] = sW[kk][tx * 4 + j];
#pragma unroll
            for (int i = 0; i < 8; i++) xv[i] = sX[ty * 8 + i][kk];
#pragma unroll
            for (int i = 0; i < 8; i++) {
                acc[i][0] = __fmaf_rn(xv[i], wv[0], acc[i][0]);
                acc[i][1] = __fmaf_rn(xv[i], wv[1], acc[i][1]);
                acc[i][2] = __fmaf_rn(xv[i], wv[2], acc[i][2]);
                acc[i][3] = __fmaf_rn(xv[i], wv[3], acc[i][3]);
            }
        }
        __syncthreads();
    }

    // write C + stage in smem for the score fold
#pragma unroll
    for (int i = 0; i < 8; i++) {
        int r = ty * 8 + i;
        int grow = rowBase + r;
        sC[r][tx * 4 + 0] = acc[i][0];
        sC[r][tx * 4 + 1] = acc[i][1];
        sC[r][tx * 4 + 2] = acc[i][2];
        sC[r][tx * 4 + 3] = acc[i][3];
        if (grow < M) {
            float4 o; o.x = acc[i][0]; o.y = acc[i][1]; o.z = acc[i][2]; o.w = acc[i][3];
            *(float4*)(C + (size_t)grow * F_OUT + tx * 4) = o;
        }
    }
    __syncthreads();

    if (tid < 128) {
        int grow = rowBase + tid;
        if (grow < M) {
            // Eigen 3.4 row-major gemv: 4 packet accumulators x 4 lanes
            float c[4][4];
#pragma unroll
            for (int q = 0; q < 4; q++)
#pragma unroll
                for (int l = 0; l < 4; l++) c[q][l] = 0.f;
#pragma unroll
            for (int p = 0; p < 4; p++) {          // j = 16p
#pragma unroll
                for (int q = 0; q < 4; q++) {      // packet q at j + 4q
#pragma unroll
                    for (int l = 0; l < 4; l++) {  // lane l
                        int n = 16 * p + 4 * q + l;
                        c[q][l] = __fmaf_rn(sC[tid][n], sA[n], c[q][l]);
                    }
                }
            }
            // padd(padd(c0,c1), padd(c2,c3)) per lane
            float v[4];
#pragma unroll
            for (int l = 0; l < 4; l++)
                v[l] = __fadd_rn(__fadd_rn(c[0][l], c[1][l]),
                                 __fadd_rn(c[2][l], c[3][l]));
            // predux = vaddvq: (v0+v1) + (v2+v3)
            score[grow] = __fadd_rn(__fadd_rn(v[0], v[1]),
                                    __fadd_rn(v[2], v[3]));
        }
    }
}

// ---------------- pass A: edge values + per-segment id push ----------------
__global__ void edge_pass_a(const int* __restrict__ row, const int* __restrict__ col, int nnz)
{
    int stride = gridDim.x * blockDim.x;
    for (int e = blockIdx.x * blockDim.x + threadIdx.x; e < nnz; e += stride) {
        int r = row[e], c = col[e];
        float sc = __fadd_rn(g_s_score[c], g_t_score[r]);
        float ed = sc >= 0.f ? sc : __fmul_rn(0.2f, sc);   // leaky relu 0.2
        g_edge[e] = ed;
        int pr = atomicAdd(&g_row_cnt[r], 1);
        if (pr < CAP_ROW) g_row_ids[(size_t)r * CAP_ROW + pr] = e;
        int pc = atomicAdd(&g_col_cnt[c], 1);
        if (pc < CAP_COL) g_col_ids[(size_t)c * CAP_COL + pc] = e;
    }
}

// ---------------- fold: per-segment ascending-e fp32 fold ----------------
template <int CAP>
__device__ __forceinline__ float fold_segment(const int* list, int cnt)
{
    int ids[CAP];
    for (int i = 0; i < cnt; i++) ids[i] = list[i];
    for (int i = 1; i < cnt; i++) {           // nearly-sorted -> cheap
        int v = ids[i], j = i - 1;
        while (j >= 0 && ids[j] > v) { ids[j + 1] = ids[j]; j--; }
        ids[j + 1] = v;
    }
    float s = 0.f;
    for (int i = 0; i < cnt; i++) s = __fadd_rn(s, g_edge[ids[i]]);
    return s;
}

__global__ void fold_rows(int n_t) {
    int seg = blockIdx.x * blockDim.x + threadIdx.x;
    if (seg >= n_t) return;
    int cnt = min(g_row_cnt[seg], CAP_ROW);
    g_e_row_sum[seg] = fold_segment<CAP_ROW>(g_row_ids + (size_t)seg * CAP_ROW, cnt);
}

__global__ void fold_cols(int n_s) {
    int seg = blockIdx.x * blockDim.x + threadIdx.x;
    if (seg >= n_s) return;
    int cnt = min(g_col_cnt[seg], CAP_COL);
    g_f_row_sum[seg] = fold_segment<CAP_COL>(g_col_ids + (size_t)seg * CAP_COL, cnt);
}

// ---------------- pass B: normalized scatter of 64-wide messages ----------------
__global__ void __launch_bounds__(256) edge_pass_b(
    const int* __restrict__ row, const int* __restrict__ col,
    const float* __restrict__ nbhd,
    float* __restrict__ msg_src, float* __restrict__ msg_tgt, int nnz)
{
    long long t = (long long)blockIdx.x * blockDim.x + threadIdx.x;
    int e = (int)(t >> 4);
    if (e >= nnz) return;
    int q = (int)(t & 15);

    int r = row[e], c = col[e];
    float ed  = g_edge[e];
    float nv  = nbhd[e];
    float ers = g_e_row_sum[r];
    float frs = g_f_row_sum[c];
    float ev = __fmul_rn(__fdiv_rn(ed, ers == 0.f ? 1.f : ers), nv);
    float fv = __fmul_rn(__fdiv_rn(ed, frs == 0.f ? 1.f : frs), nv);

    const float4 sm = *(const float4*)(g_s_msg + (size_t)c * F_OUT + q * 4);
    red_add_v4(msg_tgt + (size_t)r * F_OUT + q * 4,
               __fmul_rn(ev, sm.x), __fmul_rn(ev, sm.y),
               __fmul_rn(ev, sm.z), __fmul_rn(ev, sm.w));

    const float4 tm = *(const float4*)(g_t_msg + (size_t)r * F_OUT + q * 4);
    red_add_v4(msg_src + (size_t)c * F_OUT + q * 4,
               __fmul_rn(fv, tm.x), __fmul_rn(fv, tm.y),
               __fmul_rn(fv, tm.z), __fmul_rn(fv, tm.w));
}

// ---------------- launch ----------------
extern "C" void kernel_launch(void* const* d_in, const int* in_sizes, int n_in,
                              void* d_out, int out_size)
{
    (void)n_in;
    const float* x_s  = (const float*)d_in[0];
    const float* x_t  = (const float*)d_in[1];
    const float* nbhd = (const float*)d_in[2];
    const float* w_s  = (const float*)d_in[3];
    const float* w_t  = (const float*)d_in[4];
    const float* att  = (const float*)d_in[5];
    const int*   row  = (const int*)d_in[6];
    const int*   col  = (const int*)d_in[7];

    const int n_s = in_sizes[0] / D_IN;
    const int n_t = in_sizes[1] / D_IN;
    const int nnz = in_sizes[2];

    float* out = (float*)d_out;
    float* msg_src = out;                              // (n_s, 64)
    float* msg_tgt = out + (size_t)n_s * F_OUT;        // (n_t, 64)

    float* p_s_msg;   cudaGetSymbolAddress((void**)&p_s_msg,   g_s_msg);
    float* p_t_msg;   cudaGetSymbolAddress((void**)&p_t_msg,   g_t_msg);
    float* p_s_score; cudaGetSymbolAddress((void**)&p_s_score, g_s_score);
    float* p_t_score; cudaGetSymbolAddress((void**)&p_t_score, g_t_score);

    zero_kernel<<<2048, 256>>>((float4*)d_out, out_size / 4, n_t, n_s);

    gemm_fused<<<(n_s + 127) / 128, 256>>>(x_s, w_s, att,          p_s_msg, p_s_score, n_s);
    gemm_fused<<<(n_t + 127) / 128, 256>>>(x_t, w_t, att + F_OUT,  p_t_msg, p_t_score, n_t);

    edge_pass_a<<<(nnz + 255) / 256, 256>>>(row, col, nnz);

    fold_rows<<<(n_t + 127) / 128, 128>>>(n_t);
    fold_cols<<<(n_s + 127) / 128, 128>>>(n_s);

    long long total = (long long)nnz * 16;
    int blocksB = (int)((total + 255) / 256);
    edge_pass_b<<<blocksB, 256>>>(row, col, nbhd, msg_src, msg_tgt, nnz);
}